// round 14
// baseline (speedup 1.0000x reference)
#include <cuda_runtime.h>

// y = s1 * FWHT( g * FWHT( s2 * x ) ) per token, D = 4096.
// Two tokens per register pair (f32x2 packed math), 16 u64/thread.
// ZERO shuffles: all 24 butterfly stages in registers, reached via
//   2 CTA-wide exchanges (X1/X2, R12's proven sigma map) and
//   2 warp-local exchanges (X1.5, map tau inside the warp's 512-elem block).
//   L0 : regs i8-11, lanes i0-4, warps i5-7      (coalesced global I/O)
//   L1 : regs i4-7,  lanes {i0-3,i8}, warps i9-11
//   L1b: regs i0-3,  lanes {i4-7,i8}, warps i9-11
// sigma(i) = i0_3 | (i4^i8)<<4 | i5_7<<5 | i8<<8 | i9_11<<9   (X1/X2)
// tau(j)   = (i0_3^i4_7) | i4_7<<4 | i8<<8   within block w    (X1.5)
// All STS/LDS half-warp bank-bijective; sigma L1-side lives entirely in
// block w -> X1.5 needs only __syncwarp.

#define DDIM 4096
#define PAIRS 4           // token-pairs per CTA -> 8 tokens/CTA
#define NEG1 0xBF800000BF800000ULL

typedef unsigned long long u64;

__device__ __forceinline__ u64 pk2(float lo, float hi) {
    u64 u; asm("mov.b64 %0,{%1,%2};" : "=l"(u) : "f"(lo), "f"(hi)); return u;
}
__device__ __forceinline__ void up2(u64 u, float& a, float& b) {
    asm("mov.b64 {%0,%1},%2;" : "=f"(a), "=f"(b) : "l"(u));
}
__device__ __forceinline__ u64 add2(u64 a, u64 b) {
    u64 r; asm("add.rn.f32x2 %0,%1,%2;" : "=l"(r) : "l"(a), "l"(b)); return r;
}
__device__ __forceinline__ u64 mul2(u64 a, u64 b) {
    u64 r; asm("mul.rn.f32x2 %0,%1,%2;" : "=l"(r) : "l"(a), "l"(b)); return r;
}
__device__ __forceinline__ u64 fma2(u64 a, u64 b, u64 c) {
    u64 r; asm("fma.rn.f32x2 %0,%1,%2,%3;" : "=l"(r) : "l"(a), "l"(b), "l"(c)); return r;
}
__device__ __forceinline__ void bstep(u64& a, u64& c) {
    u64 s = add2(a, c);
    u64 d = fma2(c, NEG1, a);
    a = s; c = d;
}
__device__ __forceinline__ void bfly4p(u64 U[16]) {
#pragma unroll
    for (int b = 1; b < 16; b <<= 1)
#pragma unroll
        for (int r = 0; r < 16; r++)
            if (!(r & b)) bstep(U[r], U[r | b]);
}

__device__ __forceinline__ float softplus_f(float x) {
    return fmaxf(x, 0.0f) + log1pf(expf(-fabsf(x)));
}

__global__ void __launch_bounds__(256, 3)
whvi_kernel(const float* __restrict__ x,
            const float* __restrict__ s1,
            const float* __restrict__ s2,
            const float* __restrict__ g_mu,
            const float* __restrict__ g_rho,
            const float* __restrict__ eps,
            float* __restrict__ out,
            int n_tokens)
{
    __shared__ u64   sh2[DDIM];    // 32 KB packed exchange buffer
    __shared__ float gbuf[DDIM];   // 16 KB g_tilde (warp-private map)

    const int t = threadIdx.x;     // 0..255 ; L0: t = i0-7
    const int l = t & 31;
    const int w = t >> 5;

    // sigma bases (as in R12):
    //   L0 side: addr0(r) = t ^ ((r&1)*0x110) ^ ((r>>1)<<9)   (r = i8-11)
    //   L1 side: addr  = rb ^ (r<<4)                          (r = i4-7)
    const int rb = (l & 15) | ((l >> 4) << 4) | ((l >> 4) << 8) | (w << 9);
    // tau bases (warp block):
    const int wb15 = (w << 9) | (l & 15) | ((l >> 4) << 8);          // L1 side
    const int rb15 = (w << 9) | ((l & 15) * 17) | ((l >> 4) << 8);   // L1b side
    // g buffer base (banks = l, thread-private addresses)
    const int gb = (w << 9) | l;

    // ---- g_tilde once per CTA (thread writes exactly what it later reads) ----
#pragma unroll
    for (int r = 0; r < 16; r++) {
        const int i = r | ((l & 15) << 4) | ((l >> 4) << 8) | (w << 9);
        gbuf[gb | (r << 5)] = g_mu[i] + softplus_f(g_rho[i]) * eps[i];
    }

    const int tokA0 = blockIdx.x * (2 * PAIRS);

    for (int ip = 0; ip < PAIRS; ip++) {
        const int tokA = tokA0 + 2 * ip;
        if (tokA >= n_tokens) break;
        const int  tokB = tokA + 1;
        const bool hasB = (tokB < n_tokens);

        const float* __restrict__ xA = x + (size_t)tokA * DDIM;
        const float* __restrict__ xB = hasB ? x + (size_t)tokB * DDIM : xA;

        // ---- load both tokens, * s2, pack ----  (L0: elem i = t + 256r)
        u64 U[16];
#pragma unroll
        for (int r = 0; r < 16; r++) {
            const int i = t + (r << 8);
            const float s = s2[i];
            U[r] = pk2(xA[i] * s, xB[i] * s);
        }

        bfly4p(U);                                  // FWHT1 i8-11

        // ---- X1: L0 -> L1 (CTA-wide) ----
        __syncthreads();                            // WAR vs prev pair X2 reads
#pragma unroll
        for (int r = 0; r < 16; r++)
            sh2[t ^ ((r & 1) * 0x110) ^ ((r >> 1) << 9)] = U[r];
        __syncthreads();
#pragma unroll
        for (int r = 0; r < 16; r++)
            U[r] = sh2[rb ^ (r << 4)];

        bfly4p(U);                                  // FWHT1 i4-7

        // ---- X1.5: L1 -> L1b (warp-local, block w) ----
        __syncwarp();                               // all lanes done X1-reads of block w
#pragma unroll
        for (int r = 0; r < 16; r++)
            sh2[wb15 ^ (17 * r)] = U[r];
        __syncwarp();
#pragma unroll
        for (int r = 0; r < 16; r++)
            U[r] = sh2[rb15 ^ r];

        bfly4p(U);                                  // FWHT1 i0-3  (FWHT1 done)

        // ---- * g_tilde ----
#pragma unroll
        for (int r = 0; r < 16; r++) {
            const float g = gbuf[gb | (r << 5)];
            U[r] = mul2(U[r], pk2(g, g));
        }

        bfly4p(U);                                  // FWHT2 i0-3

        // ---- X1.5 back: L1b -> L1 (warp-local) ----
        // writes go to the exact addresses this thread just read (self-owned)
#pragma unroll
        for (int r = 0; r < 16; r++)
            sh2[rb15 ^ r] = U[r];
        __syncwarp();
#pragma unroll
        for (int r = 0; r < 16; r++)
            U[r] = sh2[wb15 ^ (17 * r)];

        bfly4p(U);                                  // FWHT2 i4-7

        // ---- X2: L1 -> L0 (CTA-wide) ----
        __syncwarp();                               // lanes done X1.5back reads of block w
#pragma unroll
        for (int r = 0; r < 16; r++)
            sh2[rb ^ (r << 4)] = U[r];
        __syncthreads();
#pragma unroll
        for (int r = 0; r < 16; r++)
            U[r] = sh2[t ^ ((r & 1) * 0x110) ^ ((r >> 1) << 9)];

        bfly4p(U);                                  // FWHT2 i8-11

        // ---- * s1, unpack, store both tokens (coalesced) ----
        float* __restrict__ oA = out + (size_t)tokA * DDIM;
        float* __restrict__ oB = out + (size_t)tokB * DDIM;
#pragma unroll
        for (int r = 0; r < 16; r++) {
            const int i = t + (r << 8);
            const float s = s1[i];
            float a, b; up2(U[r], a, b);
            oA[i] = a * s;
            if (hasB) oB[i] = b * s;
        }
    }
}

extern "C" void kernel_launch(void* const* d_in, const int* in_sizes, int n_in,
                              void* d_out, int out_size)
{
    const float* x     = (const float*)d_in[0];
    const float* s1    = (const float*)d_in[1];
    const float* s2    = (const float*)d_in[2];
    const float* g_mu  = (const float*)d_in[3];
    const float* g_rho = (const float*)d_in[4];
    const float* eps   = (const float*)d_in[5];
    // d_in[6] = H, unused

    float* out = (float*)d_out;
    const int n_tokens = in_sizes[0] / DDIM;
    const int per_cta = 2 * PAIRS;
    const int grid = (n_tokens + per_cta - 1) / per_cta;

    whvi_kernel<<<grid, 256>>>(x, s1, s2, g_mu, g_rho, eps, out, n_tokens);
}

// round 15
// speedup vs baseline: 1.0638x; 1.0638x over previous
#include <cuda_runtime.h>

// y = s1 * FWHT( g * FWHT( s2 * x ) ) per token, D = 4096.
// R12 dataflow (proven, 89.2us best) with a register diet to reach 4 CTAs/SM:
//   __launch_bounds__(256,4) (64-reg cap), u64-native shuffles, folded
//   addressing. Two tokens per register pair (f32x2 packed math).
//   L0: regs i8-11, lanes i0-4, warps i5-7      (coalesced global I/O)
//   L1: regs i4-7,  lanes {i0-3, i8}, warps i9-11
// FWHT1 = bfly4(i8-11) . X1 . bfly4(i4-7) . shfl(i0-3)
// *g, FWHT2 = shfl(i0-3) . bfly4(i4-7) . X2 . bfly4(i8-11)
// sigma(i) = i0_3 | (i4^i8)<<4 | i5_7<<5 | i8<<8 | i9_11<<9 (bank-bijective
// on both sides; round-trip verified in R12/R13 runs, rel_err 1.15e-6).

#define DDIM 4096
#define PAIRS 4           // token-pairs per CTA -> 8 tokens/CTA
#define NEG1 0xBF800000BF800000ULL

typedef unsigned long long u64;

__device__ __forceinline__ u64 pk2(float lo, float hi) {
    u64 u; asm("mov.b64 %0,{%1,%2};" : "=l"(u) : "f"(lo), "f"(hi)); return u;
}
__device__ __forceinline__ void up2(u64 u, float& a, float& b) {
    asm("mov.b64 {%0,%1},%2;" : "=f"(a), "=f"(b) : "l"(u));
}
__device__ __forceinline__ u64 add2(u64 a, u64 b) {
    u64 r; asm("add.rn.f32x2 %0,%1,%2;" : "=l"(r) : "l"(a), "l"(b)); return r;
}
__device__ __forceinline__ u64 mul2(u64 a, u64 b) {
    u64 r; asm("mul.rn.f32x2 %0,%1,%2;" : "=l"(r) : "l"(a), "l"(b)); return r;
}
__device__ __forceinline__ u64 fma2(u64 a, u64 b, u64 c) {
    u64 r; asm("fma.rn.f32x2 %0,%1,%2,%3;" : "=l"(r) : "l"(a), "l"(b), "l"(c)); return r;
}
__device__ __forceinline__ void bstep(u64& a, u64& c) {
    u64 s = add2(a, c);
    u64 d = fma2(c, NEG1, a);
    a = s; c = d;
}
__device__ __forceinline__ void bfly4p(u64 U[16]) {
#pragma unroll
    for (int b = 1; b < 16; b <<= 1)
#pragma unroll
        for (int r = 0; r < 16; r++)
            if (!(r & b)) bstep(U[r], U[r | b]);
}

__device__ __forceinline__ float softplus_f(float x) {
    return fmaxf(x, 0.0f) + log1pf(expf(-fabsf(x)));
}

__global__ void __launch_bounds__(256, 4)
whvi_kernel(const float* __restrict__ x,
            const float* __restrict__ s1,
            const float* __restrict__ s2,
            const float* __restrict__ g_mu,
            const float* __restrict__ g_rho,
            const float* __restrict__ eps,
            float* __restrict__ out,
            int n_tokens)
{
    __shared__ u64   sh2[DDIM];    // 32 KB packed exchange buffer (sigma)
    __shared__ float gbuf[DDIM];   // 16 KB g_tilde at sigma (L1-side) addresses

    const int t = threadIdx.x;     // 0..255 ; L0: t = i0-7
    const int l = t & 31;
    const int w = t >> 5;

    // sigma bases:
    //  L0 side: addr(r) = t ^ ((r&1)*0x110) ^ ((r>>1)<<9)   (r = i8-11)
    //  L1 side: addr(r) = rb ^ (r<<4)                       (r = i4-7)
    const int rb = (l & 15) | ((l >> 4) << 4) | ((l >> 4) << 8) | (w << 9);

    // ---- g_tilde once per CTA at sigma L1-side addresses ----
#pragma unroll
    for (int r = 0; r < 16; r++) {
        const int i = (l & 15) | (r << 4) | ((l >> 4) << 8) | (w << 9);
        gbuf[rb ^ (r << 4)] = g_mu[i] + softplus_f(g_rho[i]) * eps[i];
    }
    // visible before first read via pair-0's X1 barriers

    const int tokA0 = blockIdx.x * (2 * PAIRS);

    for (int ip = 0; ip < PAIRS; ip++) {
        const int tokA = tokA0 + 2 * ip;
        if (tokA >= n_tokens) break;
        const bool hasB = (tokA + 1 < n_tokens);

        const float* __restrict__ xA = x + (size_t)tokA * DDIM;

        // ---- load both tokens, * s2, pack ----  (L0: elem i = t + 256r)
        u64 U[16];
#pragma unroll
        for (int r = 0; r < 16; r++) {
            const int i = t + (r << 8);
            const float s = s2[i];
            const float a = xA[i] * s;
            const float b = hasB ? xA[i + DDIM] * s : 0.0f;
            U[r] = pk2(a, b);
        }

        bfly4p(U);                                  // FWHT1 bits 8-11

        // ---- X1: L0 -> L1 ----
        __syncthreads();                            // WAR vs prev pair X2 reads
#pragma unroll
        for (int r = 0; r < 16; r++)
            sh2[t ^ ((r & 1) * 0x110) ^ ((r >> 1) << 9)] = U[r];
        __syncthreads();
#pragma unroll
        for (int r = 0; r < 16; r++)
            U[r] = sh2[rb ^ (r << 4)];

        bfly4p(U);                                  // FWHT1 bits 4-7

        // ---- FWHT1 shuffles: bits 0-3 (u64-native) ----
#pragma unroll
        for (int s = 0; s < 4; s++) {
            const int m = 1 << s;
            const float sg = (l & m) ? -1.0f : 1.0f;
            const u64 sg2 = pk2(sg, sg);
#pragma unroll
            for (int r = 0; r < 16; r++) {
                const u64 p = __shfl_xor_sync(0xffffffffu, U[r], m);
                U[r] = fma2(U[r], sg2, p);
            }
        }

        // ---- * g_tilde (sigma addresses, conflict-free) ----
#pragma unroll
        for (int r = 0; r < 16; r++) {
            const float g = gbuf[rb ^ (r << 4)];
            U[r] = mul2(U[r], pk2(g, g));
        }

        // ---- FWHT2 shuffles: bits 0-3 ----
#pragma unroll
        for (int s = 0; s < 4; s++) {
            const int m = 1 << s;
            const float sg = (l & m) ? -1.0f : 1.0f;
            const u64 sg2 = pk2(sg, sg);
#pragma unroll
            for (int r = 0; r < 16; r++) {
                const u64 p = __shfl_xor_sync(0xffffffffu, U[r], m);
                U[r] = fma2(U[r], sg2, p);
            }
        }

        bfly4p(U);                                  // FWHT2 bits 4-7

        // ---- X2: L1 -> L0 ----
        __syncthreads();                            // WAR vs X1/g reads
#pragma unroll
        for (int r = 0; r < 16; r++)
            sh2[rb ^ (r << 4)] = U[r];
        __syncthreads();
#pragma unroll
        for (int r = 0; r < 16; r++)
            U[r] = sh2[t ^ ((r & 1) * 0x110) ^ ((r >> 1) << 9)];

        bfly4p(U);                                  // FWHT2 bits 8-11

        // ---- * s1, unpack, store both tokens (coalesced) ----
        float* __restrict__ oA = out + (size_t)tokA * DDIM;
#pragma unroll
        for (int r = 0; r < 16; r++) {
            const int i = t + (r << 8);
            const float s = s1[i];
            float a, b; up2(U[r], a, b);
            oA[i] = a * s;
            if (hasB) oA[i + DDIM] = b * s;
        }
    }
}

extern "C" void kernel_launch(void* const* d_in, const int* in_sizes, int n_in,
                              void* d_out, int out_size)
{
    const float* x     = (const float*)d_in[0];
    const float* s1    = (const float*)d_in[1];
    const float* s2    = (const float*)d_in[2];
    const float* g_mu  = (const float*)d_in[3];
    const float* g_rho = (const float*)d_in[4];
    const float* eps   = (const float*)d_in[5];
    // d_in[6] = H, unused

    float* out = (float*)d_out;
    const int n_tokens = in_sizes[0] / DDIM;
    const int per_cta = 2 * PAIRS;
    const int grid = (n_tokens + per_cta - 1) / per_cta;

    whvi_kernel<<<grid, 256>>>(x, s1, s2, g_mu, g_rho, eps, out, n_tokens);
}